// round 9
// baseline (speedup 1.0000x reference)
#include <cuda_runtime.h>
#include <cuda_bf16.h>
#include <cstdint>

#define COULOMB_K   14.3996454784936f
#define N_CAP       524288
#define BLOCK       256

// u16 fixed-point sigma^2 table: q = sigma^2 * 16384  (sigma^2 < 2.26)
__device__ unsigned short g_sig2[N_CAP];

// ---------------- prologue: quantize sigma^2 (8/thread) + zero out; trigger early ----------------
__global__ void prep_kernel(const float4* __restrict__ sigma4,
                            float4* __restrict__ out4, int n8) {
    int i = blockIdx.x * blockDim.x + threadIdx.x;
    if (i < n8) {
        float4 a = __ldg(sigma4 + 2 * i);
        float4 b = __ldg(sigma4 + 2 * i + 1);
        uint4 v;
        v.x = (__float2uint_rn(a.x * a.x * 16384.0f) & 0xFFFFu) |
              (__float2uint_rn(a.y * a.y * 16384.0f) << 16);
        v.y = (__float2uint_rn(a.z * a.z * 16384.0f) & 0xFFFFu) |
              (__float2uint_rn(a.w * a.w * 16384.0f) << 16);
        v.z = (__float2uint_rn(b.x * b.x * 16384.0f) & 0xFFFFu) |
              (__float2uint_rn(b.y * b.y * 16384.0f) << 16);
        v.w = (__float2uint_rn(b.z * b.z * 16384.0f) & 0xFFFFu) |
              (__float2uint_rn(b.w * b.w * 16384.0f) << 16);
        reinterpret_cast<uint4*>(g_sig2)[i] = v;
        float4 z = make_float4(0.f, 0.f, 0.f, 0.f);
        out4[2 * i]     = z;
        out4[2 * i + 1] = z;
    }
    __threadfence();
    cudaTriggerProgrammaticLaunchCompletion();
}
__global__ void prep_tail_kernel(const float* __restrict__ sigma,
                                 float* __restrict__ out, int start, int n) {
    int i = start + threadIdx.x;
    if (i < n) {
        float s = sigma[i];
        unsigned int q = __float2uint_rn(s * s * 16384.0f);
        g_sig2[i] = (unsigned short)(q > 65535u ? 65535u : q);
        out[i] = 0.0f;
    }
}

__device__ __forceinline__ unsigned short tbl(int idx) {
    return __ldg(&g_sig2[idx]);
}

// usum = q(ss^2)+q(sd^2);  2*(ss^2+sd^2) = usum / 8192
__device__ __forceinline__ void edge_compute(float r, uint32_t usum, int d,
                                             float* __restrict__ out) {
    float g2  = (float)usum * (1.0f / 8192.0f);
    float arg = r * rsqrtf(g2);                  // r / (sqrt2 * gamma)
    float x = r * 0.2f;                          // r / CUTOFF
    float p = fmaf(-6.0f, x, 15.0f);
    p = fmaf(p, x, -10.0f);
    float fcut = fmaf(x * x * x, p, 1.0f);       // 1 -10x^3 +15x^4 -6x^5
    fcut = (r <= 5.0f) ? fcut : 0.0f;
    float t = erff(arg) * fcut * __fdividef(1.0f, r);
    atomicAdd(out + d, t);                        // RED (no return)
}

// 8 edges/thread: streams first (independent of prep), gridsync, gathers, REDs
__global__ void __launch_bounds__(BLOCK)
edge_kernel(const float* __restrict__ bond,
            const int*   __restrict__ src,
            const int*   __restrict__ dst,
            float*       __restrict__ out,
            int n8) {
    int t = blockIdx.x * BLOCK + threadIdx.x;
    if (t >= n8) {
        cudaGridDependencySynchronize();
        __threadfence();
        cudaTriggerProgrammaticLaunchCompletion();
        return;
    }
    long base = (long)t * 2;   // in float4 groups

    const float4* bond4 = reinterpret_cast<const float4*>(bond);
    const int4*   src4  = reinterpret_cast<const int4*>(src);
    const int4*   dst4  = reinterpret_cast<const int4*>(dst);

    // streaming loads: independent of prep output — issue before gridsync
    float4 rA = __ldcs(bond4 + base);
    float4 rB = __ldcs(bond4 + base + 1);
    int4   sA = __ldcs(src4 + base);
    int4   sB = __ldcs(src4 + base + 1);
    int4   dA = __ldcs(dst4 + base);
    int4   dB = __ldcs(dst4 + base + 1);

    // wait for prep's table + zeroed output to be visible
    cudaGridDependencySynchronize();

    // all 16 gathers issued contiguously (MLP over L2 latency)
    unsigned short ss0 = tbl(sA.x), ss1 = tbl(sA.y), ss2 = tbl(sA.z), ss3 = tbl(sA.w);
    unsigned short ss4 = tbl(sB.x), ss5 = tbl(sB.y), ss6 = tbl(sB.z), ss7 = tbl(sB.w);
    unsigned short sd0 = tbl(dA.x), sd1 = tbl(dA.y), sd2 = tbl(dA.z), sd3 = tbl(dA.w);
    unsigned short sd4 = tbl(dB.x), sd5 = tbl(dB.y), sd6 = tbl(dB.z), sd7 = tbl(dB.w);

    edge_compute(rA.x, (uint32_t)ss0 + sd0, dA.x, out);
    edge_compute(rA.y, (uint32_t)ss1 + sd1, dA.y, out);
    edge_compute(rA.z, (uint32_t)ss2 + sd2, dA.z, out);
    edge_compute(rA.w, (uint32_t)ss3 + sd3, dA.w, out);
    edge_compute(rB.x, (uint32_t)ss4 + sd4, dB.x, out);
    edge_compute(rB.y, (uint32_t)ss5 + sd5, dB.y, out);
    edge_compute(rB.z, (uint32_t)ss6 + sd6, dB.z, out);
    edge_compute(rB.w, (uint32_t)ss7 + sd7, dB.w, out);

    __threadfence();
    cudaTriggerProgrammaticLaunchCompletion();
}

__global__ void edge_tail_kernel(const float* __restrict__ bond,
                                 const int*   __restrict__ src,
                                 const int*   __restrict__ dst,
                                 float*       __restrict__ out,
                                 int start, int n_edges) {
    int e = start + blockIdx.x * blockDim.x + threadIdx.x;
    if (e < n_edges) {
        uint32_t a = (uint32_t)tbl(src[e]) + (uint32_t)tbl(dst[e]);
        edge_compute(bond[e], a, dst[e], out);
    }
}

// ---------------- epilogue: out[i] *= K * charge[i]  (8/thread, PDL) ----------------
__global__ void scale_kernel(const float4* __restrict__ charge4,
                             float4* __restrict__ out4, int n8) {
    cudaGridDependencySynchronize();
    int i = blockIdx.x * blockDim.x + threadIdx.x;
    if (i >= n8) return;
#pragma unroll
    for (int k = 0; k < 2; k++) {
        float4 c = __ldg(charge4 + 2 * i + k);
        float4 o = out4[2 * i + k];
        o.x *= COULOMB_K * c.x;
        o.y *= COULOMB_K * c.y;
        o.z *= COULOMB_K * c.z;
        o.w *= COULOMB_K * c.w;
        out4[2 * i + k] = o;
    }
}
__global__ void scale_tail_kernel(const float* __restrict__ charge,
                                  float* __restrict__ out, int start, int n) {
    int i = start + threadIdx.x;
    if (i < n) out[i] *= COULOMB_K * charge[i];
}

static void launch_pdl(void* fn, dim3 grid, dim3 block,
                       void** args, cudaStream_t stream) {
    cudaLaunchConfig_t cfg = {};
    cfg.gridDim = grid;
    cfg.blockDim = block;
    cfg.stream = stream;
    cudaLaunchAttribute at[1];
    at[0].id = cudaLaunchAttributeProgrammaticStreamSerialization;
    at[0].val.programmaticStreamSerializationAllowed = 1;
    cfg.attrs = at;
    cfg.numAttrs = 1;
    cudaLaunchKernelExC(&cfg, fn, args);
}

extern "C" void kernel_launch(void* const* d_in, const int* in_sizes, int n_in,
                              void* d_out, int out_size) {
    const float* charge    = (const float*)d_in[0];
    const float* sigma     = (const float*)d_in[1];
    const float* bond_dist = (const float*)d_in[2];
    const int*   src       = (const int*)d_in[3];
    const int*   dst       = (const int*)d_in[4];
    float* out = (float*)d_out;

    int n_nodes = in_sizes[0];
    int n_edges = in_sizes[2];

    // ---- prologue (normal launch) ----
    int nn8 = n_nodes / 8;
    {
        const float4* s4 = reinterpret_cast<const float4*>(sigma);
        float4* o4 = reinterpret_cast<float4*>(out);
        prep_kernel<<<(nn8 + BLOCK - 1) / BLOCK, BLOCK>>>(s4, o4, nn8);
    }
    if (nn8 * 8 < n_nodes)
        prep_tail_kernel<<<1, 256>>>(sigma, out, nn8 * 8, n_nodes);

    // ---- edge kernel (PDL: overlaps prep) ----
    int n8 = n_edges / 8;
    if (n8 > 0) {
        int blocks = (n8 + BLOCK - 1) / BLOCK;
        void* args[] = {(void*)&bond_dist, (void*)&src, (void*)&dst,
                        (void*)&out, (void*)&n8};
        launch_pdl((void*)edge_kernel, dim3(blocks), dim3(BLOCK), args, 0);
    }
    if (n8 * 8 < n_edges) {
        int tail = n_edges - n8 * 8;
        edge_tail_kernel<<<(tail + BLOCK - 1) / BLOCK, BLOCK>>>(
            bond_dist, src, dst, out, n8 * 8, n_edges);
    }

    // ---- epilogue (PDL: overlaps edge-kernel tail / launch gap) ----
    {
        const float4* c4 = reinterpret_cast<const float4*>(charge);
        float4* o4 = reinterpret_cast<float4*>(out);
        int blocks = (nn8 + BLOCK - 1) / BLOCK;
        void* args[] = {(void*)&c4, (void*)&o4, (void*)&nn8};
        launch_pdl((void*)scale_kernel, dim3(blocks), dim3(BLOCK), args, 0);
    }
    if (nn8 * 8 < n_nodes)
        scale_tail_kernel<<<1, 256>>>(charge, out, nn8 * 8, n_nodes);
}

// round 10
// speedup vs baseline: 1.1682x; 1.1682x over previous
#include <cuda_runtime.h>
#include <cuda_bf16.h>
#include <cstdint>

#define COULOMB_K 14.3996454784936f
#define BLOCK     256

// ---------------- prologue: zero output (float4) ----------------
__global__ void zero_kernel(float4* __restrict__ out4, int n4) {
    int i = blockIdx.x * blockDim.x + threadIdx.x;
    if (i < n4) out4[i] = make_float4(0.f, 0.f, 0.f, 0.f);
}
__global__ void zero_tail_kernel(float* __restrict__ out, int start, int n) {
    int i = start + threadIdx.x;
    if (i < n) out[i] = 0.0f;
}

// message: erf(r/(sqrt2*gamma)) * fcut(r) / r   (K*charge[dst] folded into epilogue)
__device__ __forceinline__ void edge_compute(float r, float ss, float sd, int d,
                                             float* __restrict__ out) {
    float g2  = 2.0f * fmaf(ss, ss, sd * sd);    // 2*(ss^2+sd^2)
    float arg = r * rsqrtf(g2);                  // r / (sqrt2 * gamma)
    float x = r * 0.2f;                          // r / CUTOFF
    float p = fmaf(-6.0f, x, 15.0f);
    p = fmaf(p, x, -10.0f);
    float fcut = fmaf(x * x * x, p, 1.0f);       // 1 -10x^3 +15x^4 -6x^5
    fcut = (r <= 5.0f) ? fcut : 0.0f;
    float t = erff(arg) * fcut * __fdividef(1.0f, r);
    atomicAdd(out + d, t);                       // RED (no return)
}

// 8 edges/thread: vector streams -> 16 batched gathers -> compute+RED
__global__ void __launch_bounds__(BLOCK)
edge_kernel(const float* __restrict__ bond,
            const int*   __restrict__ src,
            const int*   __restrict__ dst,
            const float* __restrict__ sigma,
            float*       __restrict__ out,
            int n8) {
    int t = blockIdx.x * BLOCK + threadIdx.x;
    if (t >= n8) return;
    long base = (long)t * 2;   // in float4 groups

    const float4* bond4 = reinterpret_cast<const float4*>(bond);
    const int4*   src4  = reinterpret_cast<const int4*>(src);
    const int4*   dst4  = reinterpret_cast<const int4*>(dst);

    // streaming loads, evict-first (don't pollute L1 for the gathers)
    float4 rA = __ldcs(bond4 + base);
    float4 rB = __ldcs(bond4 + base + 1);
    int4   sA = __ldcs(src4 + base);
    int4   sB = __ldcs(src4 + base + 1);
    int4   dA = __ldcs(dst4 + base);
    int4   dB = __ldcs(dst4 + base + 1);

    // all 16 scattered gathers issued contiguously (MLP over L2 latency)
    float ss0 = __ldg(sigma + sA.x), ss1 = __ldg(sigma + sA.y);
    float ss2 = __ldg(sigma + sA.z), ss3 = __ldg(sigma + sA.w);
    float ss4 = __ldg(sigma + sB.x), ss5 = __ldg(sigma + sB.y);
    float ss6 = __ldg(sigma + sB.z), ss7 = __ldg(sigma + sB.w);
    float sd0 = __ldg(sigma + dA.x), sd1 = __ldg(sigma + dA.y);
    float sd2 = __ldg(sigma + dA.z), sd3 = __ldg(sigma + dA.w);
    float sd4 = __ldg(sigma + dB.x), sd5 = __ldg(sigma + dB.y);
    float sd6 = __ldg(sigma + dB.z), sd7 = __ldg(sigma + dB.w);

    edge_compute(rA.x, ss0, sd0, dA.x, out);
    edge_compute(rA.y, ss1, sd1, dA.y, out);
    edge_compute(rA.z, ss2, sd2, dA.z, out);
    edge_compute(rA.w, ss3, sd3, dA.w, out);
    edge_compute(rB.x, ss4, sd4, dB.x, out);
    edge_compute(rB.y, ss5, sd5, dB.y, out);
    edge_compute(rB.z, ss6, sd6, dB.z, out);
    edge_compute(rB.w, ss7, sd7, dB.w, out);
}

__global__ void edge_tail_kernel(const float* __restrict__ bond,
                                 const int*   __restrict__ src,
                                 const int*   __restrict__ dst,
                                 const float* __restrict__ sigma,
                                 float*       __restrict__ out,
                                 int start, int n_edges) {
    int e = start + blockIdx.x * blockDim.x + threadIdx.x;
    if (e < n_edges) {
        float ss = __ldg(sigma + src[e]);
        float sd = __ldg(sigma + dst[e]);
        edge_compute(bond[e], ss, sd, dst[e], out);
    }
}

// ---------------- epilogue: out[i] *= K * charge[i] (float4) ----------------
__global__ void scale_kernel(const float4* __restrict__ charge4,
                             float4* __restrict__ out4, int n4) {
    int i = blockIdx.x * blockDim.x + threadIdx.x;
    if (i < n4) {
        float4 c = __ldg(charge4 + i);
        float4 o = out4[i];
        o.x *= COULOMB_K * c.x;
        o.y *= COULOMB_K * c.y;
        o.z *= COULOMB_K * c.z;
        o.w *= COULOMB_K * c.w;
        out4[i] = o;
    }
}
__global__ void scale_tail_kernel(const float* __restrict__ charge,
                                  float* __restrict__ out, int start, int n) {
    int i = start + threadIdx.x;
    if (i < n) out[i] *= COULOMB_K * charge[i];
}

extern "C" void kernel_launch(void* const* d_in, const int* in_sizes, int n_in,
                              void* d_out, int out_size) {
    const float* charge    = (const float*)d_in[0];
    const float* sigma     = (const float*)d_in[1];
    const float* bond_dist = (const float*)d_in[2];
    const int*   src       = (const int*)d_in[3];
    const int*   dst       = (const int*)d_in[4];
    float* out = (float*)d_out;

    int n_nodes = in_sizes[0];
    int n_edges = in_sizes[2];

    // zero output
    int nn4 = n_nodes / 4;
    zero_kernel<<<(nn4 + BLOCK - 1) / BLOCK, BLOCK>>>(
        reinterpret_cast<float4*>(out), nn4);
    if (nn4 * 4 < n_nodes)
        zero_tail_kernel<<<1, 256>>>(out, nn4 * 4, n_nodes);

    // edge accumulation (measured-optimal flat structure)
    int n8 = n_edges / 8;
    if (n8 > 0) {
        int blocks = (n8 + BLOCK - 1) / BLOCK;
        edge_kernel<<<blocks, BLOCK>>>(bond_dist, src, dst, sigma, out, n8);
    }
    if (n8 * 8 < n_edges) {
        int tail = n_edges - n8 * 8;
        edge_tail_kernel<<<(tail + BLOCK - 1) / BLOCK, BLOCK>>>(
            bond_dist, src, dst, sigma, out, n8 * 8, n_edges);
    }

    // scale by K * charge
    scale_kernel<<<(nn4 + BLOCK - 1) / BLOCK, BLOCK>>>(
        reinterpret_cast<const float4*>(charge),
        reinterpret_cast<float4*>(out), nn4);
    if (nn4 * 4 < n_nodes)
        scale_tail_kernel<<<1, 256>>>(charge, out, nn4 * 4, n_nodes);
}